// round 12
// baseline (speedup 1.0000x reference)
#include <cuda_runtime.h>
#include <math.h>

#define N_NODES 20000
#define N_EDGES 100000

typedef unsigned long long ull;

// scratch (static __device__ per harness rules)
// g_node layout per node (512 floats): [s(128) | v0(128) | v1(128) | v2(128)]
static __device__ float g_node[N_NODES * 512];
static __device__ float g_h[N_EDGES * 64];

#define SILU_NORM 1.6790390826f

__device__ __forceinline__ float act(float x) {
    return SILU_NORM * x / (1.0f + __expf(-x));
}

__device__ __forceinline__ ull pk2(float lo, float hi) {
    ull r; asm("mov.b64 %0, {%1,%2};" : "=l"(r) : "f"(lo), "f"(hi)); return r;
}
__device__ __forceinline__ void fma2(ull& d, ull a, ull b) {
    asm("fma.rn.f32x2 %0, %1, %2, %0;" : "+l"(d) : "l"(a), "l"(b));
}
__device__ __forceinline__ float rsum(ull v) {
    float lo, hi; asm("mov.b64 {%0,%1}, %2;" : "=f"(lo), "=f"(hi) : "l"(v));
    return lo + hi;
}

// ---------------------------------------------------------------------------
// Kernel 1: node up-projection (SoA output), f32x2, 2 nodes per warp.
// 256 threads / 8 warps: warp w handles nodes base+w and base+w+8 (16/iter).
// (measured 140us in R10)
// ---------------------------------------------------------------------------
__global__ void __launch_bounds__(256) node_kernel(
    const float* __restrict__ nf,
    const float* __restrict__ Wus,
    const float* __restrict__ Wuv)
{
    extern __shared__ float sm[];
    ull* sWsP = (ull*)sm;             // 8192 ull
    ull* sWvP = (ull*)(sm + 16384);   // 8192 ull
    float* snf = sm + 32768;          // 16 nodes * 512
    int t = threadIdx.x;

    for (int i = t; i < 8192; i += 256) {
        int u2 = i >> 7, c = i & 127;
        sWsP[i] = pk2(Wus[(2 * u2) * 128 + c], Wus[(2 * u2 + 1) * 128 + c]);
        sWvP[i] = pk2(Wuv[(2 * u2) * 128 + c], Wuv[(2 * u2 + 1) * 128 + c]);
    }
    __syncthreads();

    int warp = t >> 5, cg = t & 31;
    const float inv = 0.08838834764831845f; // 1/sqrt(128)

    for (int base = blockIdx.x * 16; base < N_NODES; base += gridDim.x * 16) {
        for (int i = t; i < 8192; i += 256) {
            int nd = i >> 9, ch = i & 511;
            float v = nf[(size_t)(base + nd) * 512 + ch];
            int pos;
            if (ch < 128) pos = ch;
            else { int j = ch - 128; pos = 128 + (j % 3) * 128 + j / 3; }
            snf[nd * 512 + pos] = v;
        }
        __syncthreads();

        const float* rowA = snf + warp * 512;
        const float* rowB = snf + (warp + 8) * 512;
        const ull* As = (const ull*)rowA;
        const ull* A0 = (const ull*)(rowA + 128);
        const ull* A1 = (const ull*)(rowA + 256);
        const ull* A2 = (const ull*)(rowA + 384);
        const ull* Bs = (const ull*)rowB;
        const ull* B0 = (const ull*)(rowB + 128);
        const ull* B1 = (const ull*)(rowB + 256);
        const ull* B2 = (const ull*)(rowB + 384);

        ull aA[16], aB[16];
        #pragma unroll
        for (int i = 0; i < 16; ++i) { aA[i] = 0; aB[i] = 0; }

        #pragma unroll 4
        for (int u2 = 0; u2 < 64; ++u2) {
            ulonglong2 bsA = *(const ulonglong2*)(sWsP + u2 * 128 + 4 * cg);
            ulonglong2 bsB = *(const ulonglong2*)(sWsP + u2 * 128 + 4 * cg + 2);
            ulonglong2 bvA = *(const ulonglong2*)(sWvP + u2 * 128 + 4 * cg);
            ulonglong2 bvB = *(const ulonglong2*)(sWvP + u2 * 128 + 4 * cg + 2);
            ull xs, x0, x1, x2;
            xs = As[u2]; x0 = A0[u2]; x1 = A1[u2]; x2 = A2[u2];
            fma2(aA[0],  xs, bsA.x); fma2(aA[1],  xs, bsA.y);
            fma2(aA[2],  xs, bsB.x); fma2(aA[3],  xs, bsB.y);
            fma2(aA[4],  x0, bvA.x); fma2(aA[5],  x0, bvA.y);
            fma2(aA[6],  x0, bvB.x); fma2(aA[7],  x0, bvB.y);
            fma2(aA[8],  x1, bvA.x); fma2(aA[9],  x1, bvA.y);
            fma2(aA[10], x1, bvB.x); fma2(aA[11], x1, bvB.y);
            fma2(aA[12], x2, bvA.x); fma2(aA[13], x2, bvA.y);
            fma2(aA[14], x2, bvB.x); fma2(aA[15], x2, bvB.y);
            xs = Bs[u2]; x0 = B0[u2]; x1 = B1[u2]; x2 = B2[u2];
            fma2(aB[0],  xs, bsA.x); fma2(aB[1],  xs, bsA.y);
            fma2(aB[2],  xs, bsB.x); fma2(aB[3],  xs, bsB.y);
            fma2(aB[4],  x0, bvA.x); fma2(aB[5],  x0, bvA.y);
            fma2(aB[6],  x0, bvB.x); fma2(aB[7],  x0, bvB.y);
            fma2(aB[8],  x1, bvA.x); fma2(aB[9],  x1, bvA.y);
            fma2(aB[10], x1, bvB.x); fma2(aB[11], x1, bvB.y);
            fma2(aB[12], x2, bvA.x); fma2(aB[13], x2, bvA.y);
            fma2(aB[14], x2, bvB.x); fma2(aB[15], x2, bvB.y);
        }

        float* oA = g_node + (size_t)(base + warp) * 512;
        float* oB = g_node + (size_t)(base + warp + 8) * 512;
        #pragma unroll
        for (int s = 0; s < 4; ++s) {
            float4 r;
            r.x = rsum(aA[s*4+0]) * inv; r.y = rsum(aA[s*4+1]) * inv;
            r.z = rsum(aA[s*4+2]) * inv; r.w = rsum(aA[s*4+3]) * inv;
            ((float4*)(oA + 128 * s))[cg] = r;
            r.x = rsum(aB[s*4+0]) * inv; r.y = rsum(aB[s*4+1]) * inv;
            r.z = rsum(aB[s*4+2]) * inv; r.w = rsum(aB[s*4+3]) * inv;
            ((float4*)(oB + 128 * s))[cg] = r;
        }
        __syncthreads();
    }
}

// ---------------------------------------------------------------------------
// Kernel 2: edge MLP layers 0..2 -> g_h.  128 edges/CTA, 128 threads. (R3 proven)
// ---------------------------------------------------------------------------
__global__ void __launch_bounds__(128) mlp_kernel(
    const float* __restrict__ ef,
    const float* __restrict__ w0,
    const float* __restrict__ w1,
    const float* __restrict__ w2)
{
    extern __shared__ float sm[];
    float* sw0 = sm;              // 512
    float* sw1 = sw0 + 512;       // 4096
    float* sw2 = sw1 + 4096;      // 4096
    float* sef = sw2 + 4096;      // 1024
    float* hA  = sef + 1024;      // 128*65
    float* hB  = hA + 128 * 65;   // 128*65

    int t = threadIdx.x;
    const float is8 = 0.35355339059327373f; // 1/sqrt(8)
    for (int i = t; i < 512; i += 128) sw0[i] = w0[i] * is8;
    for (int i = t; i < 4096; i += 128) { sw1[i] = w1[i] * 0.125f; sw2[i] = w2[i] * 0.125f; }
    int ebase = blockIdx.x * 128;
    int nvalid = N_EDGES - ebase; if (nvalid > 128) nvalid = 128;
    for (int i = t; i < 1024; i += 128)
        sef[i] = (i < nvalid * 8) ? ef[ebase * 8 + i] : 0.f;
    __syncthreads();

    int es = t & 31;
    int dg = t >> 5;
    float acc[4][16];

    // layer 0
    #pragma unroll
    for (int k = 0; k < 4; ++k)
        #pragma unroll
        for (int d = 0; d < 16; ++d) acc[k][d] = 0.f;
    #pragma unroll
    for (int u = 0; u < 8; ++u) {
        float x0 = sef[(es      ) * 8 + u];
        float x1 = sef[(es + 32) * 8 + u];
        float x2 = sef[(es + 64) * 8 + u];
        float x3 = sef[(es + 96) * 8 + u];
        #pragma unroll
        for (int d = 0; d < 16; ++d) {
            float w = sw0[u * 64 + dg * 16 + d];
            acc[0][d] += x0 * w; acc[1][d] += x1 * w; acc[2][d] += x2 * w; acc[3][d] += x3 * w;
        }
    }
    #pragma unroll
    for (int k = 0; k < 4; ++k)
        #pragma unroll
        for (int d = 0; d < 16; ++d)
            hA[(es + 32 * k) * 65 + dg * 16 + d] = act(acc[k][d]);
    __syncthreads();

    // layer 1
    #pragma unroll
    for (int k = 0; k < 4; ++k)
        #pragma unroll
        for (int d = 0; d < 16; ++d) acc[k][d] = 0.f;
    #pragma unroll 8
    for (int u = 0; u < 64; ++u) {
        float x0 = hA[(es      ) * 65 + u];
        float x1 = hA[(es + 32) * 65 + u];
        float x2 = hA[(es + 64) * 65 + u];
        float x3 = hA[(es + 96) * 65 + u];
        #pragma unroll
        for (int d = 0; d < 16; ++d) {
            float w = sw1[u * 64 + dg * 16 + d];
            acc[0][d] += x0 * w; acc[1][d] += x1 * w; acc[2][d] += x2 * w; acc[3][d] += x3 * w;
        }
    }
    #pragma unroll
    for (int k = 0; k < 4; ++k)
        #pragma unroll
        for (int d = 0; d < 16; ++d)
            hB[(es + 32 * k) * 65 + dg * 16 + d] = act(acc[k][d]);
    __syncthreads();

    // layer 2 -> g_h
    #pragma unroll
    for (int k = 0; k < 4; ++k)
        #pragma unroll
        for (int d = 0; d < 16; ++d) acc[k][d] = 0.f;
    #pragma unroll 8
    for (int u = 0; u < 64; ++u) {
        float x0 = hB[(es      ) * 65 + u];
        float x1 = hB[(es + 32) * 65 + u];
        float x2 = hB[(es + 64) * 65 + u];
        float x3 = hB[(es + 96) * 65 + u];
        #pragma unroll
        for (int d = 0; d < 16; ++d) {
            float w = sw2[u * 64 + dg * 16 + d];
            acc[0][d] += x0 * w; acc[1][d] += x1 * w; acc[2][d] += x2 * w; acc[3][d] += x3 * w;
        }
    }
    #pragma unroll
    for (int k = 0; k < 4; ++k) {
        int e = ebase + es + 32 * k;
        if (e < N_EDGES) {
            #pragma unroll
            for (int d = 0; d < 16; ++d)
                g_h[(size_t)e * 64 + dg * 16 + d] = act(acc[k][d]);
        }
    }
}

// ---------------------------------------------------------------------------
// Kernel 3: fused tpw + tensor product + output GEMMs. (R8 measured best)
// 32 edges/CTA, 256 threads (warp w owns edges 4w..4w+3; lane cg owns cols 4cg..+3)
// out_v factorization: out_v[e,n,i] = sh1_i * (P@Wv_top)[e,n] + ((Q*vs_i)@Wv_bot)[e,n]
// ssv uses the SoA node layout [s|v0|v1|v2] to match g_node.
// ---------------------------------------------------------------------------
__global__ void __launch_bounds__(256) edge_kernel(
    const float* __restrict__ ea,     // edge_attrs (E,4)
    const int*   __restrict__ eidx,   // edge_index (2,E): sender first
    const float* __restrict__ w3,     // (64,512)
    const float* __restrict__ Wos,    // (256,128)
    const float* __restrict__ Wov,    // (256,128)
    float* __restrict__ out)
{
    extern __shared__ float sm[];
    float* ssv = sm;                  // 32*512 = 16384 (gathered, SoA)
    float* sA  = ssv + 16384;         // 32*256 = 8192 (mid_s, coef folded)
    float* sP  = sA + 8192;           // 32*128 = 4096
    float* sQ  = sP + 4096;           // 32*128 = 4096
    float* sh  = sQ + 4096;           // 32*64  = 2048
    float* sW  = sh + 2048;           // 64*128 = 8192 (B staging)
    float* sea = sW + 8192;           // 128
    int*   snd = (int*)(sea + 128);   // 32

    const float C0 = 0.70710678118654752f / 128.0f;                       // sqrt(.5)/(8*16)
    const float C3 = 0.70710678118654752f / (128.0f * 1.7320508075688772f);

    int t = threadIdx.x;
    int warp = t >> 5;
    int cg = t & 31;
    int ebase = blockIdx.x * 32;

    if (t < 32) snd[t] = eidx[ebase + t];
    if (t >= 128 && t < 256) sea[t - 128] = ea[ebase * 4 + (t - 128)];
    __syncthreads();

    { // gather node rows (32 x 512 floats, 8 threads/row, float4)
        int r = t >> 3, q = t & 7;
        const float4* src = (const float4*)g_node + (size_t)snd[r] * 128;
        float4* dst = (float4*)ssv + r * 128;
        #pragma unroll
        for (int j = 0; j < 16; ++j) dst[q + 8 * j] = src[q + 8 * j];
    }
    { // h tile (512 float4)
        const float4* src = (const float4*)g_h + (size_t)ebase * 16;
        float4* dst = (float4*)sh;
        dst[t] = src[t];
        dst[t + 256] = src[t + 256];
    }
    __syncthreads();

    int e0 = warp * 4;
    const float4* w34 = (const float4*)w3;
    float4* sW4 = (float4*)sW;

    // ---- tpw chunks -> A / P / Q (coefficients folded) ----
    for (int c = 0; c < 4; ++c) {
        #pragma unroll
        for (int j = 0; j < 8; ++j) {
            int idx = t + 256 * j;           // < 2048
            int u = idx >> 5, q = idx & 31;
            sW4[idx] = w34[u * 128 + c * 32 + q];
        }
        __syncthreads();

        float acc[4][4];
        #pragma unroll
        for (int k = 0; k < 4; ++k) { acc[k][0]=0.f; acc[k][1]=0.f; acc[k][2]=0.f; acc[k][3]=0.f; }
        #pragma unroll 4
        for (int u = 0; u < 64; ++u) {
            float4 b = sW4[u * 32 + cg];
            #pragma unroll
            for (int k = 0; k < 4; ++k) {
                float a = sh[(e0 + k) * 64 + u];
                acc[k][0] += a * b.x; acc[k][1] += a * b.y;
                acc[k][2] += a * b.z; acc[k][3] += a * b.w;
            }
        }
        #pragma unroll
        for (int k = 0; k < 4; ++k) {
            int e = e0 + k;
            float s0 = sea[e * 4];
            if (c == 0) {
                float4 sv = ((const float4*)(ssv + e * 512))[cg];
                float4 v;
                v.x = C0 * acc[k][0] * sv.x * s0; v.y = C0 * acc[k][1] * sv.y * s0;
                v.z = C0 * acc[k][2] * sv.z * s0; v.w = C0 * acc[k][3] * sv.w * s0;
                ((float4*)sA)[e * 64 + cg] = v;
            } else if (c == 1) {
                float4 sv = ((const float4*)(ssv + e * 512))[cg];
                float4 v;
                v.x = C0 * acc[k][0] * sv.x; v.y = C0 * acc[k][1] * sv.y;
                v.z = C0 * acc[k][2] * sv.z; v.w = C0 * acc[k][3] * sv.w;
                ((float4*)sP)[e * 32 + cg] = v;
            } else if (c == 2) {
                float4 v;
                v.x = C0 * acc[k][0] * s0; v.y = C0 * acc[k][1] * s0;
                v.z = C0 * acc[k][2] * s0; v.w = C0 * acc[k][3] * s0;
                ((float4*)sQ)[e * 32 + cg] = v;
            } else {
                float s1 = sea[e * 4 + 1], s2 = sea[e * 4 + 2], s3 = sea[e * 4 + 3];
                float4 v0 = ((const float4*)(ssv + e * 512 + 128))[cg];
                float4 v1 = ((const float4*)(ssv + e * 512 + 256))[cg];
                float4 v2 = ((const float4*)(ssv + e * 512 + 384))[cg];
                float4 v;
                v.x = C3 * acc[k][0] * (v0.x * s1 + v1.x * s2 + v2.x * s3);
                v.y = C3 * acc[k][1] * (v0.y * s1 + v1.y * s2 + v2.y * s3);
                v.z = C3 * acc[k][2] * (v0.z * s1 + v1.z * s2 + v2.z * s3);
                v.w = C3 * acc[k][3] * (v0.w * s1 + v1.w * s2 + v2.w * s3);
                ((float4*)sA)[e * 64 + 32 + cg] = v;
            }
        }
        __syncthreads();
    }

    // ---- out_s = A(32x256) @ Wos(256x128) ----
    {
        float accs[4][4];
        #pragma unroll
        for (int k = 0; k < 4; ++k) { accs[k][0]=0.f; accs[k][1]=0.f; accs[k][2]=0.f; accs[k][3]=0.f; }
        const float4* Ws4 = (const float4*)Wos;
        for (int kt = 0; kt < 4; ++kt) {
            #pragma unroll
            for (int j = 0; j < 8; ++j) { int idx = t + 256 * j; sW4[idx] = Ws4[kt * 2048 + idx]; }
            __syncthreads();
            #pragma unroll 4
            for (int u = 0; u < 64; ++u) {
                float4 b = sW4[u * 32 + cg];
                #pragma unroll
                for (int k = 0; k < 4; ++k) {
                    float a = sA[(e0 + k) * 256 + kt * 64 + u];
                    accs[k][0] += a * b.x; accs[k][1] += a * b.y;
                    accs[k][2] += a * b.z; accs[k][3] += a * b.w;
                }
            }
            __syncthreads();
        }
        #pragma unroll
        for (int k = 0; k < 4; ++k) {
            size_t e = (size_t)(ebase + e0 + k);
            ((float4*)out)[e * 128 + cg] =
                make_float4(accs[k][0], accs[k][1], accs[k][2], accs[k][3]);
        }
    }

    // ---- PV = P(32x128) @ Wv_top(128x128) ----
    float accp[4][4];
    #pragma unroll
    for (int k = 0; k < 4; ++k) { accp[k][0]=0.f; accp[k][1]=0.f; accp[k][2]=0.f; accp[k][3]=0.f; }
    const float4* Wv4 = (const float4*)Wov;
    for (int kt = 0; kt < 2; ++kt) {
        #pragma unroll
        for (int j = 0; j < 8; ++j) { int idx = t + 256 * j; sW4[idx] = Wv4[kt * 2048 + idx]; }
        __syncthreads();
        #pragma unroll 4
        for (int u = 0; u < 64; ++u) {
            float4 b = sW4[u * 32 + cg];
            #pragma unroll
            for (int k = 0; k < 4; ++k) {
                float a = sP[(e0 + k) * 128 + kt * 64 + u];
                accp[k][0] += a * b.x; accp[k][1] += a * b.y;
                accp[k][2] += a * b.z; accp[k][3] += a * b.w;
            }
        }
        __syncthreads();
    }

    // ---- QV_i = (Q*vs_i) @ Wv_bot (SoA v reads) ----
    float accq[3][4][4];
    #pragma unroll
    for (int i = 0; i < 3; ++i)
        #pragma unroll
        for (int k = 0; k < 4; ++k) { accq[i][k][0]=0.f; accq[i][k][1]=0.f; accq[i][k][2]=0.f; accq[i][k][3]=0.f; }
    for (int kt = 0; kt < 2; ++kt) {
        #pragma unroll
        for (int j = 0; j < 8; ++j) { int idx = t + 256 * j; sW4[idx] = Wv4[(128 + kt * 64) * 32 + idx]; }
        __syncthreads();
        #pragma unroll 2
        for (int u = 0; u < 64; ++u) {
            float4 b = sW4[u * 32 + cg];
            int uu = kt * 64 + u;
            #pragma unroll
            for (int k = 0; k < 4; ++k) {
                int e = e0 + k;
                float q = sQ[e * 128 + uu];
                float q0 = q * ssv[e * 512 + 128 + uu];
                float q1 = q * ssv[e * 512 + 256 + uu];
                float q2 = q * ssv[e * 512 + 384 + uu];
                accq[0][k][0] += q0 * b.x; accq[0][k][1] += q0 * b.y; accq[0][k][2] += q0 * b.z; accq[0][k][3] += q0 * b.w;
                accq[1][k][0] += q1 * b.x; accq[1][k][1] += q1 * b.y; accq[1][k][2] += q1 * b.z; accq[1][k][3] += q1 * b.w;
                accq[2][k][0] += q2 * b.x; accq[2][k][1] += q2 * b.y; accq[2][k][2] += q2 * b.z; accq[2][k][3] += q2 * b.w;
            }
        }
        __syncthreads();
    }

    // ---- combine + restage out_v through smem for coalesced stores ----
    float* vbuf = sA;   // sA(8192)+sP(4096) contiguous = 12288 floats = 32*384
    #pragma unroll
    for (int k = 0; k < 4; ++k) {
        int e = e0 + k;
        float s1 = sea[e * 4 + 1], s2 = sea[e * 4 + 2], s3 = sea[e * 4 + 3];
        #pragma unroll
        for (int j = 0; j < 4; ++j) {
            int n = cg * 4 + j;
            float pvv = accp[k][j];
            vbuf[e * 384 + n * 3 + 0] = s1 * pvv + accq[0][k][j];
            vbuf[e * 384 + n * 3 + 1] = s2 * pvv + accq[1][k][j];
            vbuf[e * 384 + n * 3 + 2] = s3 * pvv + accq[2][k][j];
        }
    }
    __syncthreads();
    float4* vb4 = (float4*)vbuf;
    #pragma unroll
    for (int j = 0; j < 12; ++j) {
        int idx = t + 256 * j;      // < 3072
        int e = idx / 96, rem = idx % 96;
        ((float4*)out)[(size_t)(ebase + e) * 128 + 32 + rem] = vb4[idx];
    }
}

// ---------------------------------------------------------------------------
extern "C" void kernel_launch(void* const* d_in, const int* in_sizes, int n_in,
                              void* d_out, int out_size) {
    const float* node_feats = (const float*)d_in[0];
    const float* edge_attrs = (const float*)d_in[1];
    const float* edge_feats = (const float*)d_in[2];
    const int*   edge_index = (const int*)d_in[3];
    const float* W_up_s  = (const float*)d_in[4];
    const float* W_up_v  = (const float*)d_in[5];
    const float* mlp_w0  = (const float*)d_in[6];
    const float* mlp_w1  = (const float*)d_in[7];
    const float* mlp_w2  = (const float*)d_in[8];
    const float* mlp_w3  = (const float*)d_in[9];
    const float* W_out_s = (const float*)d_in[10];
    const float* W_out_v = (const float*)d_in[11];
    float* out = (float*)d_out;

    size_t smem1 = (size_t)40960 * 4;   // 160 KB
    size_t smem2 = (size_t)26368 * 4;   // 103 KB
    size_t smem3 = (size_t)43200 * 4;   // 168.75 KB
    cudaFuncSetAttribute(node_kernel, cudaFuncAttributeMaxDynamicSharedMemorySize, (int)smem1);
    cudaFuncSetAttribute(mlp_kernel,  cudaFuncAttributeMaxDynamicSharedMemorySize, (int)smem2);
    cudaFuncSetAttribute(edge_kernel, cudaFuncAttributeMaxDynamicSharedMemorySize, (int)smem3);

    node_kernel<<<148, 256, smem1>>>(node_feats, W_up_s, W_up_v);
    mlp_kernel<<<(N_EDGES + 127) / 128, 128, smem2>>>(edge_feats, mlp_w0, mlp_w1, mlp_w2);
    edge_kernel<<<N_EDGES / 32, 256, smem3>>>(edge_attrs, edge_index, mlp_w3,
                                              W_out_s, W_out_v, out);
}

// round 13
// speedup vs baseline: 1.5243x; 1.5243x over previous
#include <cuda_runtime.h>
#include <cuda_bf16.h>
#include <math.h>

#define N_NODES 20000
#define N_EDGES 100000
typedef unsigned long long ull;

static __device__ float g_node[N_NODES * 512]; // SoA: [s|v0|v1|v2] per node
static __device__ float g_h[N_EDGES * 64];
// pre-converted bf16 hi/lo weights, layout [n][k2] (k2 = k/2), scales folded
static __device__ __align__(16) unsigned gw3h[512 * 32], gw3l[512 * 32];
static __device__ __align__(16) unsigned gWsh[128 * 128], gWsl[128 * 128];
static __device__ __align__(16) unsigned gWvh[128 * 128], gWvl[128 * 128];

#define SILU_NORM 1.6790390826f
__device__ __forceinline__ float act(float x) { return SILU_NORM * x / (1.0f + __expf(-x)); }
__device__ __forceinline__ ull pk2(float lo, float hi) {
    ull r; asm("mov.b64 %0, {%1,%2};" : "=l"(r) : "f"(lo), "f"(hi)); return r;
}
__device__ __forceinline__ void fma2(ull& d, ull a, ull b) {
    asm("fma.rn.f32x2 %0, %1, %2, %0;" : "+l"(d) : "l"(a), "l"(b));
}
__device__ __forceinline__ float rsum(ull v) {
    float lo, hi; asm("mov.b64 {%0,%1}, %2;" : "=f"(lo), "=f"(hi) : "l"(v)); return lo + hi;
}
// split (x,y) into bf16 hi and lo packed u32 (x in low half)
__device__ __forceinline__ void cvt2(float x, float y, unsigned& h, unsigned& l) {
    __nv_bfloat16 xh = __float2bfloat16(x), yh = __float2bfloat16(y);
    __nv_bfloat162 H; H.x = xh; H.y = yh;
    __nv_bfloat162 L; L.x = __float2bfloat16(x - __bfloat162float(xh));
    L.y = __float2bfloat16(y - __bfloat162float(yh));
    h = *(unsigned*)&H; l = *(unsigned*)&L;
}
__device__ __forceinline__ void mma4(float4& d, unsigned a0, unsigned a1, unsigned a2, unsigned a3,
                                     unsigned b0, unsigned b1) {
    asm volatile("mma.sync.aligned.m16n8k16.row.col.f32.bf16.bf16.f32 "
        "{%0,%1,%2,%3},{%4,%5,%6,%7},{%8,%9},{%0,%1,%2,%3};"
        : "+f"(d.x), "+f"(d.y), "+f"(d.z), "+f"(d.w)
        : "r"(a0), "r"(a1), "r"(a2), "r"(a3), "r"(b0), "r"(b1));
}

// ---------------------------------------------------------------------------
__global__ void prep_kernel(const float* __restrict__ w3, const float* __restrict__ Wos,
                            const float* __restrict__ Wov) {
    int i = blockIdx.x * 256 + threadIdx.x;   // < 49152
    if (i < 16384) {                           // w3 (64,512), scale 1/8
        int n = i >> 5, k2 = i & 31;
        cvt2(w3[(2 * k2) * 512 + n] * 0.125f, w3[(2 * k2 + 1) * 512 + n] * 0.125f,
             gw3h[i], gw3l[i]);
    } else if (i < 32768) {                    // Wos (256,128), scale 1/16
        int j = i - 16384; int n = j >> 7, k2 = j & 127;
        cvt2(Wos[(2 * k2) * 128 + n] * 0.0625f, Wos[(2 * k2 + 1) * 128 + n] * 0.0625f,
             gWsh[j], gWsl[j]);
    } else {                                   // Wov (256,128), scale 1/16
        int j = i - 32768; int n = j >> 7, k2 = j & 127;
        cvt2(Wov[(2 * k2) * 128 + n] * 0.0625f, Wov[(2 * k2 + 1) * 128 + n] * 0.0625f,
             gWvh[j], gWvl[j]);
    }
}

// ---------------------------------------------------------------------------
// Kernel 1: node up-projection (R10 best: 140us) — unchanged.
// ---------------------------------------------------------------------------
__global__ void __launch_bounds__(256) node_kernel(
    const float* __restrict__ nf, const float* __restrict__ Wus, const float* __restrict__ Wuv)
{
    extern __shared__ float sm[];
    ull* sWsP = (ull*)sm; ull* sWvP = (ull*)(sm + 16384);
    float* snf = sm + 32768;
    int t = threadIdx.x;
    for (int i = t; i < 8192; i += 256) {
        int u2 = i >> 7, c = i & 127;
        sWsP[i] = pk2(Wus[(2 * u2) * 128 + c], Wus[(2 * u2 + 1) * 128 + c]);
        sWvP[i] = pk2(Wuv[(2 * u2) * 128 + c], Wuv[(2 * u2 + 1) * 128 + c]);
    }
    __syncthreads();
    int warp = t >> 5, cg = t & 31;
    const float inv = 0.08838834764831845f;
    for (int base = blockIdx.x * 16; base < N_NODES; base += gridDim.x * 16) {
        for (int i = t; i < 8192; i += 256) {
            int nd = i >> 9, ch = i & 511;
            float v = nf[(size_t)(base + nd) * 512 + ch];
            int pos;
            if (ch < 128) pos = ch;
            else { int j = ch - 128; pos = 128 + (j % 3) * 128 + j / 3; }
            snf[nd * 512 + pos] = v;
        }
        __syncthreads();
        const float* rowA = snf + warp * 512;
        const float* rowB = snf + (warp + 8) * 512;
        const ull *As = (const ull*)rowA, *A0 = (const ull*)(rowA + 128),
                  *A1 = (const ull*)(rowA + 256), *A2 = (const ull*)(rowA + 384);
        const ull *Bs = (const ull*)rowB, *B0 = (const ull*)(rowB + 128),
                  *B1 = (const ull*)(rowB + 256), *B2 = (const ull*)(rowB + 384);
        ull aA[16], aB[16];
        #pragma unroll
        for (int i = 0; i < 16; ++i) { aA[i] = 0; aB[i] = 0; }
        #pragma unroll 4
        for (int u2 = 0; u2 < 64; ++u2) {
            ulonglong2 bsA = *(const ulonglong2*)(sWsP + u2 * 128 + 4 * cg);
            ulonglong2 bsB = *(const ulonglong2*)(sWsP + u2 * 128 + 4 * cg + 2);
            ulonglong2 bvA = *(const ulonglong2*)(sWvP + u2 * 128 + 4 * cg);
            ulonglong2 bvB = *(const ulonglong2*)(sWvP + u2 * 128 + 4 * cg + 2);
            ull xs, x0, x1, x2;
            xs = As[u2]; x0 = A0[u2]; x1 = A1[u2]; x2 = A2[u2];
            fma2(aA[0],  xs, bsA.x); fma2(aA[1],  xs, bsA.y);
            fma2(aA[2],  xs, bsB.x); fma2(aA[3],  xs, bsB.y);
            fma2(aA[4],  x0, bvA.x); fma2(aA[5],  x0, bvA.y);
            fma2(aA[6],  x0, bvB.x); fma2(aA[7],  x0, bvB.y);
            fma2(aA[8],  x1, bvA.x); fma2(aA[9],  x1, bvA.y);
            fma2(aA[10], x1, bvB.x); fma2(aA[11], x1, bvB.y);
            fma2(aA[12], x2, bvA.x); fma2(aA[13], x2, bvA.y);
            fma2(aA[14], x2, bvB.x); fma2(aA[15], x2, bvB.y);
            xs = Bs[u2]; x0 = B0[u2]; x1 = B1[u2]; x2 = B2[u2];
            fma2(aB[0],  xs, bsA.x); fma2(aB[1],  xs, bsA.y);
            fma2(aB[2],  xs, bsB.x); fma2(aB[3],  xs, bsB.y);
            fma2(aB[4],  x0, bvA.x); fma2(aB[5],  x0, bvA.y);
            fma2(aB[6],  x0, bvB.x); fma2(aB[7],  x0, bvB.y);
            fma2(aB[8],  x1, bvA.x); fma2(aB[9],  x1, bvA.y);
            fma2(aB[10], x1, bvB.x); fma2(aB[11], x1, bvB.y);
            fma2(aB[12], x2, bvA.x); fma2(aB[13], x2, bvA.y);
            fma2(aB[14], x2, bvB.x); fma2(aB[15], x2, bvB.y);
        }
        float* oA = g_node + (size_t)(base + warp) * 512;
        float* oB = g_node + (size_t)(base + warp + 8) * 512;
        #pragma unroll
        for (int s = 0; s < 4; ++s) {
            float4 r;
            r.x = rsum(aA[s*4+0]) * inv; r.y = rsum(aA[s*4+1]) * inv;
            r.z = rsum(aA[s*4+2]) * inv; r.w = rsum(aA[s*4+3]) * inv;
            ((float4*)(oA + 128 * s))[cg] = r;
            r.x = rsum(aB[s*4+0]) * inv; r.y = rsum(aB[s*4+1]) * inv;
            r.z = rsum(aB[s*4+2]) * inv; r.w = rsum(aB[s*4+3]) * inv;
            ((float4*)(oB + 128 * s))[cg] = r;
        }
        __syncthreads();
    }
}

// ---------------------------------------------------------------------------
// Kernel 2: edge MLP (R3 proven) — unchanged.
// ---------------------------------------------------------------------------
__global__ void __launch_bounds__(128) mlp_kernel(
    const float* __restrict__ ef, const float* __restrict__ w0,
    const float* __restrict__ w1, const float* __restrict__ w2)
{
    extern __shared__ float sm[];
    float* sw0 = sm; float* sw1 = sw0 + 512; float* sw2 = sw1 + 4096;
    float* sef = sw2 + 4096; float* hA = sef + 1024; float* hB = hA + 128 * 65;
    int t = threadIdx.x;
    const float is8 = 0.35355339059327373f;
    for (int i = t; i < 512; i += 128) sw0[i] = w0[i] * is8;
    for (int i = t; i < 4096; i += 128) { sw1[i] = w1[i] * 0.125f; sw2[i] = w2[i] * 0.125f; }
    int ebase = blockIdx.x * 128;
    int nvalid = N_EDGES - ebase; if (nvalid > 128) nvalid = 128;
    for (int i = t; i < 1024; i += 128)
        sef[i] = (i < nvalid * 8) ? ef[ebase * 8 + i] : 0.f;
    __syncthreads();
    int es = t & 31, dg = t >> 5;
    float acc[4][16];
    #pragma unroll
    for (int k = 0; k < 4; ++k)
        #pragma unroll
        for (int d = 0; d < 16; ++d) acc[k][d] = 0.f;
    #pragma unroll
    for (int u = 0; u < 8; ++u) {
        float x0 = sef[es * 8 + u], x1 = sef[(es + 32) * 8 + u];
        float x2 = sef[(es + 64) * 8 + u], x3 = sef[(es + 96) * 8 + u];
        #pragma unroll
        for (int d = 0; d < 16; ++d) {
            float w = sw0[u * 64 + dg * 16 + d];
            acc[0][d] += x0 * w; acc[1][d] += x1 * w; acc[2][d] += x2 * w; acc[3][d] += x3 * w;
        }
    }
    #pragma unroll
    for (int k = 0; k < 4; ++k)
        #pragma unroll
        for (int d = 0; d < 16; ++d) hA[(es + 32 * k) * 65 + dg * 16 + d] = act(acc[k][d]);
    __syncthreads();
    #pragma unroll
    for (int k = 0; k < 4; ++k)
        #pragma unroll
        for (int d = 0; d < 16; ++d) acc[k][d] = 0.f;
    #pragma unroll 8
    for (int u = 0; u < 64; ++u) {
        float x0 = hA[es * 65 + u], x1 = hA[(es + 32) * 65 + u];
        float x2 = hA[(es + 64) * 65 + u], x3 = hA[(es + 96) * 65 + u];
        #pragma unroll
        for (int d = 0; d < 16; ++d) {
            float w = sw1[u * 64 + dg * 16 + d];
            acc[0][d] += x0 * w; acc[1][d] += x1 * w; acc[2][d] += x2 * w; acc[3][d] += x3 * w;
        }
    }
    #pragma unroll
    for (int k = 0; k < 4; ++k)
        #pragma unroll
        for (int d = 0; d < 16; ++d) hB[(es + 32 * k) * 65 + dg * 16 + d] = act(acc[k][d]);
    __syncthreads();
    #pragma unroll
    for (int k = 0; k < 4; ++k)
        #pragma unroll
        for (int d = 0; d < 16; ++d) acc[k][d] = 0.f;
    #pragma unroll 8
    for (int u = 0; u < 64; ++u) {
        float x0 = hB[es * 65 + u], x1 = hB[(es + 32) * 65 + u];
        float x2 = hB[(es + 64) * 65 + u], x3 = hB[(es + 96) * 65 + u];
        #pragma unroll
        for (int d = 0; d < 16; ++d) {
            float w = sw2[u * 64 + dg * 16 + d];
            acc[0][d] += x0 * w; acc[1][d] += x1 * w; acc[2][d] += x2 * w; acc[3][d] += x3 * w;
        }
    }
    #pragma unroll
    for (int k = 0; k < 4; ++k) {
        int e = ebase + es + 32 * k;
        if (e < N_EDGES)
            #pragma unroll
            for (int d = 0; d < 16; ++d) g_h[(size_t)e * 64 + dg * 16 + d] = act(acc[k][d]);
    }
}

// ---------------------------------------------------------------------------
// Kernel 3: tensor-core edge kernel. 32 edges/CTA, 8 warps.
// warp w: mtb=16*(w&1), nb=32*(w>>1). bf16-split mma m16n8k16.
// ---------------------------------------------------------------------------
__device__ __forceinline__ void stageW(unsigned* Bh, unsigned* Bl,
        const unsigned* __restrict__ gh, const unsigned* __restrict__ gl, int k2o, int t) {
    #pragma unroll
    for (int j = 0; j < 4; ++j) {
        int idx = t + 256 * j;                 // < 1024
        int n = idx >> 3, m = idx & 7;
        uint4 a = *(const uint4*)&gh[n * 128 + k2o + 4 * m];
        uint4 b = *(const uint4*)&gl[n * 128 + k2o + 4 * m];
        unsigned* dh = &Bh[n * 36 + 4 * m];
        dh[0] = a.x; dh[1] = a.y; dh[2] = a.z; dh[3] = a.w;
        unsigned* dl = &Bl[n * 36 + 4 * m];
        dl[0] = b.x; dl[1] = b.y; dl[2] = b.z; dl[3] = b.w;
    }
}
// one K=64 block of bf16-split mma into cf[4]
__device__ __forceinline__ void gemm64(float4* cf,
        const unsigned* __restrict__ Ah, const unsigned* __restrict__ Al, int strA, int k2o,
        int mtb, const unsigned* __restrict__ Bh, const unsigned* __restrict__ Bl,
        int nb, int lane) {
    int gid = lane >> 2, qr = lane & 3;
    int rA = (mtb + gid) * strA + k2o, rA8 = rA + 8 * strA;
    #pragma unroll
    for (int kt = 0; kt < 4; ++kt) {
        int ka = kt * 8 + qr;
        unsigned ah0 = Ah[rA + ka],  ah1 = Ah[rA8 + ka];
        unsigned ah2 = Ah[rA + ka + 4], ah3 = Ah[rA8 + ka + 4];
        unsigned al0 = Al[rA + ka],  al1 = Al[rA8 + ka];
        unsigned al2 = Al[rA + ka + 4], al3 = Al[rA8 + ka + 4];
        #pragma unroll
        for (int j = 0; j < 4; ++j) {
            int nB = (nb + 8 * j + gid) * 36 + ka;
            unsigned bh0 = Bh[nB], bh1 = Bh[nB + 4];
            unsigned bl0 = Bl[nB], bl1 = Bl[nB + 4];
            mma4(cf[j], ah0, ah1, ah2, ah3, bh0, bh1);
            mma4(cf[j], ah0, ah1, ah2, ah3, bl0, bl1);
            mma4(cf[j], al0, al1, al2, al3, bh0, bh1);
        }
    }
}
#define Z4(a) { a[0]=make_float4(0,0,0,0); a[1]=make_float4(0,0,0,0); \
                a[2]=make_float4(0,0,0,0); a[3]=make_float4(0,0,0,0); }

__global__ void __launch_bounds__(256) edge_kernel(
    const float* __restrict__ ea, const int* __restrict__ eidx, float* __restrict__ out)
{
    extern __shared__ float sm[];
    float* ssv = sm;                           // 16384
    float* sea = sm + 16384;                   // 128
    int*   snd = (int*)(sm + 16512);           // 32
    unsigned* hAh = (unsigned*)(sm + 16544);   // 32*36
    unsigned* hAl = (unsigned*)(sm + 17696);
    unsigned* Ah  = (unsigned*)(sm + 18848);   // 32*132
    unsigned* Al  = (unsigned*)(sm + 23072);
    unsigned* Ph  = (unsigned*)(sm + 27296);   // 32*68
    unsigned* Pl  = (unsigned*)(sm + 29472);
    unsigned* Qb  = (unsigned*)(sm + 31648);   // 3 * (2176 h + 2176 l)
    unsigned* Bsh = (unsigned*)(sm + 44704);   // 128*36
    unsigned* Bsl = (unsigned*)(sm + 49312);   // end 53920 fl

    const float C0n = 0.70710678118654752f;    // sqrt(.5)
    const float C3n = 0.40824829046386302f;    // sqrt(.5)/sqrt(3)

    int t = threadIdx.x, lane = t & 31, w = t >> 5;
    int mtb = (w & 1) * 16, nb = (w >> 1) * 32;
    int gid = lane >> 2, qr = lane & 3;
    int ebase = blockIdx.x * 32;

    if (t < 32) snd[t] = eidx[ebase + t];
    if (t >= 128) sea[t - 128] = ea[ebase * 4 + (t - 128)];
    __syncthreads();
    {   // gather node rows
        int r = t >> 3, q = t & 7;
        const float4* src = (const float4*)g_node + (size_t)snd[r] * 128;
        float4* dst = (float4*)ssv + r * 128;
        #pragma unroll
        for (int j = 0; j < 16; ++j) dst[q + 8 * j] = src[q + 8 * j];
    }
    #pragma unroll
    for (int j = 0; j < 4; ++j) {              // h -> bf16 hi/lo
        int idx = t + 256 * j;
        int e = idx >> 5, k2 = idx & 31;
        float2 hv = *(const float2*)(g_h + (size_t)(ebase + e) * 64 + 2 * k2);
        cvt2(hv.x, hv.y, hAh[e * 36 + k2], hAl[e * 36 + k2]);
    }

    // ---- tpw chunks -> A / P / Q (bf16 A-operands, coefficients folded) ----
    for (int c = 0; c < 4; ++c) {
        __syncthreads();
        #pragma unroll
        for (int j = 0; j < 4; ++j) {          // stage w3 chunk c
            int idx = t + 256 * j;
            int n = idx >> 3, m = idx & 7;
            uint4 a = *(const uint4*)&gw3h[(128 * c + n) * 32 + 4 * m];
            uint4 b = *(const uint4*)&gw3l[(128 * c + n) * 32 + 4 * m];
            unsigned* dh = &Bsh[n * 36 + 4 * m];
            dh[0] = a.x; dh[1] = a.y; dh[2] = a.z; dh[3] = a.w;
            unsigned* dl = &Bsl[n * 36 + 4 * m];
            dl[0] = b.x; dl[1] = b.y; dl[2] = b.z; dl[3] = b.w;
        }
        __syncthreads();
        float4 cf[4]; Z4(cf);
        gemm64(cf, hAh, hAl, 36, 0, mtb, Bsh, Bsl, nb, lane);
        #pragma unroll
        for (int j = 0; j < 4; ++j) {
            int col = nb + 8 * j + 2 * qr;
            int k2t = col >> 1;
            #pragma unroll
            for (int hh = 0; hh < 2; ++hh) {
                int r = mtb + gid + 8 * hh;
                float cx = hh ? cf[j].z : cf[j].x;
                float cy = hh ? cf[j].w : cf[j].y;
                const float* row = ssv + r * 512;
                float s0 = sea[r * 4];
                unsigned uh, ul;
                if (c == 0) {
                    cvt2(C0n * s0 * cx * row[col], C0n * s0 * cy * row[col + 1], uh, ul);
                    Ah[r * 132 + k2t] = uh; Al[r * 132 + k2t] = ul;
                } else if (c == 1) {
                    cvt2(C0n * cx * row[col], C0n * cy * row[col + 1], uh, ul);
                    Ph[r * 68 + k2t] = uh; Pl[r * 68 + k2t] = ul;
                } else if (c == 2) {
                    float b = C0n * s0;
                    #pragma unroll
                    for (int i = 0; i < 3; ++i) {
                        cvt2(b * cx * row[128 + 128 * i + col],
                             b * cy * row[128 + 128 * i + col + 1], uh, ul);
                        Qb[i * 4352 + r * 68 + k2t] = uh;
                        Qb[i * 4352 + 2176 + r * 68 + k2t] = ul;
                    }
                } else {
                    float s1 = sea[r*4+1], s2 = sea[r*4+2], s3 = sea[r*4+3];
                    float dx = row[128+col]*s1 + row[256+col]*s2 + row[384+col]*s3;
                    float dy = row[129+col]*s1 + row[257+col]*s2 + row[385+col]*s3;
                    cvt2(C3n * cx * dx, C3n * cy * dy, uh, ul);
                    Ah[r * 132 + 64 + k2t] = uh; Al[r * 132 + 64 + k2t] = ul;
                }
            }
        }
    }

    // ---- out_s = A(32x256) @ Wos ----
    {
        float4 cs[4]; Z4(cs);
        for (int kt = 0; kt < 4; ++kt) {
            __syncthreads();
            stageW(Bsh, Bsl, gWsh, gWsl, 32 * kt, t);
            __syncthreads();
            gemm64(cs, Ah, Al, 132, 32 * kt, mtb, Bsh, Bsl, nb, lane);
        }
        #pragma unroll
        for (int j = 0; j < 4; ++j) {
            int col = nb + 8 * j + 2 * qr;
            *(float2*)&out[(size_t)(ebase + mtb + gid) * 512 + col] =
                make_float2(cs[j].x, cs[j].y);
            *(float2*)&out[(size_t)(ebase + mtb + gid + 8) * 512 + col] =
                make_float2(cs[j].z, cs[j].w);
        }
    }

    // ---- PV = P @ WvTop ----
    float4 cp[4]; Z4(cp);
    for (int s = 0; s < 2; ++s) {
        __syncthreads();
        stageW(Bsh, Bsl, gWvh, gWvl, 32 * s, t);
        __syncthreads();
        gemm64(cp, Ph, Pl, 68, 32 * s, mtb, Bsh, Bsl, nb, lane);
    }
    // ---- QV_i = (Q*v_i) @ WvBot ----
    float4 c0[4], c1[4], c2[4]; Z4(c0); Z4(c1); Z4(c2);
    for (int s = 0; s < 2; ++s) {
        __syncthreads();
        stageW(Bsh, Bsl, gWvh, gWvl, 64 + 32 * s, t);
        __syncthreads();
        gemm64(c0, Qb,        Qb + 2176, 68, 32 * s, mtb, Bsh, Bsl, nb, lane);
        gemm64(c1, Qb + 4352, Qb + 6528, 68, 32 * s, mtb, Bsh, Bsl, nb, lane);
        gemm64(c2, Qb + 8704, Qb + 10880, 68, 32 * s, mtb, Bsh, Bsl, nb, lane);
    }
    // ---- combine + store out_v ----
    #pragma unroll
    for (int j = 0; j < 4; ++j) {
        int col = nb + 8 * j + 2 * qr;
        #pragma unroll
        for (int hh = 0; hh < 2; ++hh) {
            int r = mtb + gid + 8 * hh;
            float s1 = sea[r*4+1], s2 = sea[r*4+2], s3 = sea[r*4+3];
            float px  = hh ? cp[j].z : cp[j].x,  py  = hh ? cp[j].w : cp[j].y;
            float q0x = hh ? c0[j].z : c0[j].x,  q0y = hh ? c0[j].w : c0[j].y;
            float q1x = hh ? c1[j].z : c1[j].x,  q1y = hh ? c1[j].w : c1[j].y;
            float q2x = hh ? c2[j].z : c2[j].x,  q2y = hh ? c2[j].w : c2[j].y;
            float* o = out + (size_t)(ebase + r) * 512 + 128 + col * 3;
            o[0] = s1 * px + q0x; o[1] = s2 * px + q1x; o[2] = s3 * px + q2x;
            o[3] = s1 * py + q0y; o[4] = s2 * py + q1y; o[5] = s3 * py + q2y;
        }
    }
}

// ---------------------------------------------------------------------------
extern "C" void kernel_launch(void* const* d_in, const int* in_sizes, int n_in,
                              void* d_out, int out_size) {
    const float* node_feats = (const float*)d_in[0];
    const float* edge_attrs = (const float*)d_in[1];
    const float* edge_feats = (const float*)d_in[2];
    const int*   edge_index = (const int*)d_in[3];
    const float* W_up_s  = (const float*)d_in[4];
    const float* W_up_v  = (const float*)d_in[5];
    const float* mlp_w0  = (const float*)d_in[6];
    const float* mlp_w1  = (const float*)d_in[7];
    const float* mlp_w2  = (const float*)d_in[8];
    const float* mlp_w3  = (const float*)d_in[9];
    const float* W_out_s = (const float*)d_in[10];
    const float* W_out_v = (const float*)d_in[11];
    float* out = (float*)d_out;

    size_t smem1 = (size_t)40960 * 4;   // 160 KB
    size_t smem2 = (size_t)26368 * 4;   // 103 KB
    size_t smem3 = (size_t)53920 * 4;   // 210.6 KB
    cudaFuncSetAttribute(node_kernel, cudaFuncAttributeMaxDynamicSharedMemorySize, (int)smem1);
    cudaFuncSetAttribute(mlp_kernel,  cudaFuncAttributeMaxDynamicSharedMemorySize, (int)smem2);
    cudaFuncSetAttribute(edge_kernel, cudaFuncAttributeMaxDynamicSharedMemorySize, (int)smem3);

    node_kernel<<<148, 256, smem1>>>(node_feats, W_up_s, W_up_v);
    prep_kernel<<<192, 256>>>(mlp_w3, W_out_s, W_out_v);
    mlp_kernel<<<(N_EDGES + 127) / 128, 128, smem2>>>(edge_feats, mlp_w0, mlp_w1, mlp_w2);
    edge_kernel<<<N_EDGES / 32, 256, smem3>>>(edge_attrs, edge_index, out);
}

// round 16
// speedup vs baseline: 1.7293x; 1.1345x over previous
#include <cuda_runtime.h>
#include <cuda_bf16.h>
#include <math.h>

#define N_NODES 20000
#define N_EDGES 100000
typedef unsigned long long ull;

static __device__ float g_node[N_NODES * 512]; // SoA: [s|v0|v1|v2] per node
static __device__ float g_h[N_EDGES * 64];
// pre-converted bf16 hi/lo weights, layout [n][k2] (k2 = k/2), scales folded
static __device__ __align__(16) unsigned gw3h[512 * 32], gw3l[512 * 32];
static __device__ __align__(16) unsigned gWsh[128 * 128], gWsl[128 * 128];
static __device__ __align__(16) unsigned gWvh[128 * 128], gWvl[128 * 128];

#define SILU_NORM 1.6790390826f
__device__ __forceinline__ float act(float x) { return SILU_NORM * x / (1.0f + __expf(-x)); }
__device__ __forceinline__ ull pk2(float lo, float hi) {
    ull r; asm("mov.b64 %0, {%1,%2};" : "=l"(r) : "f"(lo), "f"(hi)); return r;
}
__device__ __forceinline__ void fma2(ull& d, ull a, ull b) {
    asm("fma.rn.f32x2 %0, %1, %2, %0;" : "+l"(d) : "l"(a), "l"(b));
}
__device__ __forceinline__ float rsum(ull v) {
    float lo, hi; asm("mov.b64 {%0,%1}, %2;" : "=f"(lo), "=f"(hi) : "l"(v)); return lo + hi;
}
// split (x,y) into bf16 hi and lo packed u32 (x in low half)
__device__ __forceinline__ void cvt2(float x, float y, unsigned& h, unsigned& l) {
    __nv_bfloat16 xh = __float2bfloat16(x), yh = __float2bfloat16(y);
    __nv_bfloat162 H; H.x = xh; H.y = yh;
    __nv_bfloat162 L; L.x = __float2bfloat16(x - __bfloat162float(xh));
    L.y = __float2bfloat16(y - __bfloat162float(yh));
    h = *(unsigned*)&H; l = *(unsigned*)&L;
}
__device__ __forceinline__ void mma4(float4& d, unsigned a0, unsigned a1, unsigned a2, unsigned a3,
                                     unsigned b0, unsigned b1) {
    asm volatile("mma.sync.aligned.m16n8k16.row.col.f32.bf16.bf16.f32 "
        "{%0,%1,%2,%3},{%4,%5,%6,%7},{%8,%9},{%0,%1,%2,%3};"
        : "+f"(d.x), "+f"(d.y), "+f"(d.z), "+f"(d.w)
        : "r"(a0), "r"(a1), "r"(a2), "r"(a3), "r"(b0), "r"(b1));
}

// ---------------------------------------------------------------------------
__global__ void prep_kernel(const float* __restrict__ w3, const float* __restrict__ Wos,
                            const float* __restrict__ Wov) {
    int i = blockIdx.x * 256 + threadIdx.x;   // < 49152
    if (i < 16384) {                           // w3 (64,512), scale 1/8
        int n = i >> 5, k2 = i & 31;
        cvt2(w3[(2 * k2) * 512 + n] * 0.125f, w3[(2 * k2 + 1) * 512 + n] * 0.125f,
             gw3h[i], gw3l[i]);
    } else if (i < 32768) {                    // Wos (256,128), scale 1/16
        int j = i - 16384; int n = j >> 7, k2 = j & 127;
        cvt2(Wos[(2 * k2) * 128 + n] * 0.0625f, Wos[(2 * k2 + 1) * 128 + n] * 0.0625f,
             gWsh[j], gWsl[j]);
    } else {                                   // Wov (256,128), scale 1/16
        int j = i - 32768; int n = j >> 7, k2 = j & 127;
        cvt2(Wov[(2 * k2) * 128 + n] * 0.0625f, Wov[(2 * k2 + 1) * 128 + n] * 0.0625f,
             gWvh[j], gWvl[j]);
    }
}

// ---------------------------------------------------------------------------
// Kernel 1: node up-projection (R10 best: 140us) — unchanged.
// ---------------------------------------------------------------------------
__global__ void __launch_bounds__(256) node_kernel(
    const float* __restrict__ nf, const float* __restrict__ Wus, const float* __restrict__ Wuv)
{
    extern __shared__ float sm[];
    ull* sWsP = (ull*)sm; ull* sWvP = (ull*)(sm + 16384);
    float* snf = sm + 32768;
    int t = threadIdx.x;
    for (int i = t; i < 8192; i += 256) {
        int u2 = i >> 7, c = i & 127;
        sWsP[i] = pk2(Wus[(2 * u2) * 128 + c], Wus[(2 * u2 + 1) * 128 + c]);
        sWvP[i] = pk2(Wuv[(2 * u2) * 128 + c], Wuv[(2 * u2 + 1) * 128 + c]);
    }
    __syncthreads();
    int warp = t >> 5, cg = t & 31;
    const float inv = 0.08838834764831845f;
    for (int base = blockIdx.x * 16; base < N_NODES; base += gridDim.x * 16) {
        for (int i = t; i < 8192; i += 256) {
            int nd = i >> 9, ch = i & 511;
            float v = nf[(size_t)(base + nd) * 512 + ch];
            int pos;
            if (ch < 128) pos = ch;
            else { int j = ch - 128; pos = 128 + (j % 3) * 128 + j / 3; }
            snf[nd * 512 + pos] = v;
        }
        __syncthreads();
        const float* rowA = snf + warp * 512;
        const float* rowB = snf + (warp + 8) * 512;
        const ull *As = (const ull*)rowA, *A0 = (const ull*)(rowA + 128),
                  *A1 = (const ull*)(rowA + 256), *A2 = (const ull*)(rowA + 384);
        const ull *Bs = (const ull*)rowB, *B0 = (const ull*)(rowB + 128),
                  *B1 = (const ull*)(rowB + 256), *B2 = (const ull*)(rowB + 384);
        ull aA[16], aB[16];
        #pragma unroll
        for (int i = 0; i < 16; ++i) { aA[i] = 0; aB[i] = 0; }
        #pragma unroll 4
        for (int u2 = 0; u2 < 64; ++u2) {
            ulonglong2 bsA = *(const ulonglong2*)(sWsP + u2 * 128 + 4 * cg);
            ulonglong2 bsB = *(const ulonglong2*)(sWsP + u2 * 128 + 4 * cg + 2);
            ulonglong2 bvA = *(const ulonglong2*)(sWvP + u2 * 128 + 4 * cg);
            ulonglong2 bvB = *(const ulonglong2*)(sWvP + u2 * 128 + 4 * cg + 2);
            ull xs, x0, x1, x2;
            xs = As[u2]; x0 = A0[u2]; x1 = A1[u2]; x2 = A2[u2];
            fma2(aA[0],  xs, bsA.x); fma2(aA[1],  xs, bsA.y);
            fma2(aA[2],  xs, bsB.x); fma2(aA[3],  xs, bsB.y);
            fma2(aA[4],  x0, bvA.x); fma2(aA[5],  x0, bvA.y);
            fma2(aA[6],  x0, bvB.x); fma2(aA[7],  x0, bvB.y);
            fma2(aA[8],  x1, bvA.x); fma2(aA[9],  x1, bvA.y);
            fma2(aA[10], x1, bvB.x); fma2(aA[11], x1, bvB.y);
            fma2(aA[12], x2, bvA.x); fma2(aA[13], x2, bvA.y);
            fma2(aA[14], x2, bvB.x); fma2(aA[15], x2, bvB.y);
            xs = Bs[u2]; x0 = B0[u2]; x1 = B1[u2]; x2 = B2[u2];
            fma2(aB[0],  xs, bsA.x); fma2(aB[1],  xs, bsA.y);
            fma2(aB[2],  xs, bsB.x); fma2(aB[3],  xs, bsB.y);
            fma2(aB[4],  x0, bvA.x); fma2(aB[5],  x0, bvA.y);
            fma2(aB[6],  x0, bvB.x); fma2(aB[7],  x0, bvB.y);
            fma2(aB[8],  x1, bvA.x); fma2(aB[9],  x1, bvA.y);
            fma2(aB[10], x1, bvB.x); fma2(aB[11], x1, bvB.y);
            fma2(aB[12], x2, bvA.x); fma2(aB[13], x2, bvA.y);
            fma2(aB[14], x2, bvB.x); fma2(aB[15], x2, bvB.y);
        }
        float* oA = g_node + (size_t)(base + warp) * 512;
        float* oB = g_node + (size_t)(base + warp + 8) * 512;
        #pragma unroll
        for (int s = 0; s < 4; ++s) {
            float4 r;
            r.x = rsum(aA[s*4+0]) * inv; r.y = rsum(aA[s*4+1]) * inv;
            r.z = rsum(aA[s*4+2]) * inv; r.w = rsum(aA[s*4+3]) * inv;
            ((float4*)(oA + 128 * s))[cg] = r;
            r.x = rsum(aB[s*4+0]) * inv; r.y = rsum(aB[s*4+1]) * inv;
            r.z = rsum(aB[s*4+2]) * inv; r.w = rsum(aB[s*4+3]) * inv;
            ((float4*)(oB + 128 * s))[cg] = r;
        }
        __syncthreads();
    }
}

// ---------------------------------------------------------------------------
// Kernel 2: edge MLP (R3 proven) — unchanged.
// ---------------------------------------------------------------------------
__global__ void __launch_bounds__(128) mlp_kernel(
    const float* __restrict__ ef, const float* __restrict__ w0,
    const float* __restrict__ w1, const float* __restrict__ w2)
{
    extern __shared__ float sm[];
    float* sw0 = sm; float* sw1 = sw0 + 512; float* sw2 = sw1 + 4096;
    float* sef = sw2 + 4096; float* hA = sef + 1024; float* hB = hA + 128 * 65;
    int t = threadIdx.x;
    const float is8 = 0.35355339059327373f;
    for (int i = t; i < 512; i += 128) sw0[i] = w0[i] * is8;
    for (int i = t; i < 4096; i += 128) { sw1[i] = w1[i] * 0.125f; sw2[i] = w2[i] * 0.125f; }
    int ebase = blockIdx.x * 128;
    int nvalid = N_EDGES - ebase; if (nvalid > 128) nvalid = 128;
    for (int i = t; i < 1024; i += 128)
        sef[i] = (i < nvalid * 8) ? ef[ebase * 8 + i] : 0.f;
    __syncthreads();
    int es = t & 31, dg = t >> 5;
    float acc[4][16];
    #pragma unroll
    for (int k = 0; k < 4; ++k)
        #pragma unroll
        for (int d = 0; d < 16; ++d) acc[k][d] = 0.f;
    #pragma unroll
    for (int u = 0; u < 8; ++u) {
        float x0 = sef[es * 8 + u], x1 = sef[(es + 32) * 8 + u];
        float x2 = sef[(es + 64) * 8 + u], x3 = sef[(es + 96) * 8 + u];
        #pragma unroll
        for (int d = 0; d < 16; ++d) {
            float w = sw0[u * 64 + dg * 16 + d];
            acc[0][d] += x0 * w; acc[1][d] += x1 * w; acc[2][d] += x2 * w; acc[3][d] += x3 * w;
        }
    }
    #pragma unroll
    for (int k = 0; k < 4; ++k)
        #pragma unroll
        for (int d = 0; d < 16; ++d) hA[(es + 32 * k) * 65 + dg * 16 + d] = act(acc[k][d]);
    __syncthreads();
    #pragma unroll
    for (int k = 0; k < 4; ++k)
        #pragma unroll
        for (int d = 0; d < 16; ++d) acc[k][d] = 0.f;
    #pragma unroll 8
    for (int u = 0; u < 64; ++u) {
        float x0 = hA[es * 65 + u], x1 = hA[(es + 32) * 65 + u];
        float x2 = hA[(es + 64) * 65 + u], x3 = hA[(es + 96) * 65 + u];
        #pragma unroll
        for (int d = 0; d < 16; ++d) {
            float w = sw1[u * 64 + dg * 16 + d];
            acc[0][d] += x0 * w; acc[1][d] += x1 * w; acc[2][d] += x2 * w; acc[3][d] += x3 * w;
        }
    }
    #pragma unroll
    for (int k = 0; k < 4; ++k)
        #pragma unroll
        for (int d = 0; d < 16; ++d) hB[(es + 32 * k) * 65 + dg * 16 + d] = act(acc[k][d]);
    __syncthreads();
    #pragma unroll
    for (int k = 0; k < 4; ++k)
        #pragma unroll
        for (int d = 0; d < 16; ++d) acc[k][d] = 0.f;
    #pragma unroll 8
    for (int u = 0; u < 64; ++u) {
        float x0 = hB[es * 65 + u], x1 = hB[(es + 32) * 65 + u];
        float x2 = hB[(es + 64) * 65 + u], x3 = hB[(es + 96) * 65 + u];
        #pragma unroll
        for (int d = 0; d < 16; ++d) {
            float w = sw2[u * 64 + dg * 16 + d];
            acc[0][d] += x0 * w; acc[1][d] += x1 * w; acc[2][d] += x2 * w; acc[3][d] += x3 * w;
        }
    }
    #pragma unroll
    for (int k = 0; k < 4; ++k) {
        int e = ebase + es + 32 * k;
        if (e < N_EDGES)
            #pragma unroll
            for (int d = 0; d < 16; ++d) g_h[(size_t)e * 64 + dg * 16 + d] = act(acc[k][d]);
    }
}

// ---------------------------------------------------------------------------
// Kernel 3: tensor-core edge kernel. 32 edges/CTA, 8 warps.
// Post-TP weight staging uses a big 68-stride buffer aliasing the dead ssv/hA
// regions (full K=128 per stage, 4 stagings instead of 8). out_v restaged
// through smem (vbuf aliases Qb) for coalesced float4 stores.
// ---------------------------------------------------------------------------
// stage a 128n x 64k2 chunk, stride 68 (68 % 32 == 4 -> conflict-free frags)
__device__ __forceinline__ void stageBig(unsigned* BBh, unsigned* BBl,
        const unsigned* __restrict__ gh, const unsigned* __restrict__ gl, int k2o, int t) {
    #pragma unroll
    for (int j = 0; j < 8; ++j) {
        int idx = t + 256 * j;                 // < 2048 (uint4 units)
        int n = idx >> 4, m = idx & 15;
        uint4 a = *(const uint4*)&gh[n * 128 + k2o + 4 * m];
        uint4 b = *(const uint4*)&gl[n * 128 + k2o + 4 * m];
        *(uint4*)&BBh[n * 68 + 4 * m] = a;
        *(uint4*)&BBl[n * 68 + 4 * m] = b;
    }
}
// one K=64 block of bf16-split mma into cf[4]; A k2-offset and B k2-offset separate
__device__ __forceinline__ void gemmK(float4* cf,
        const unsigned* __restrict__ Ah, const unsigned* __restrict__ Al, int strA, int k2A,
        const unsigned* __restrict__ Bh, const unsigned* __restrict__ Bl, int strB, int k2B,
        int mtb, int nb, int lane) {
    int gid = lane >> 2, qr = lane & 3;
    int rA = (mtb + gid) * strA + k2A, rA8 = rA + 8 * strA;
    #pragma unroll
    for (int kt = 0; kt < 4; ++kt) {
        int ka = kt * 8 + qr;
        unsigned ah0 = Ah[rA + ka],  ah1 = Ah[rA8 + ka];
        unsigned ah2 = Ah[rA + ka + 4], ah3 = Ah[rA8 + ka + 4];
        unsigned al0 = Al[rA + ka],  al1 = Al[rA8 + ka];
        unsigned al2 = Al[rA + ka + 4], al3 = Al[rA8 + ka + 4];
        #pragma unroll
        for (int j = 0; j < 4; ++j) {
            int nB = (nb + 8 * j + gid) * strB + k2B + ka;
            unsigned bh0 = Bh[nB], bh1 = Bh[nB + 4];
            unsigned bl0 = Bl[nB], bl1 = Bl[nB + 4];
            mma4(cf[j], ah0, ah1, ah2, ah3, bh0, bh1);
            mma4(cf[j], ah0, ah1, ah2, ah3, bl0, bl1);
            mma4(cf[j], al0, al1, al2, al3, bh0, bh1);
        }
    }
}
#define Z4(a) { a[0]=make_float4(0,0,0,0); a[1]=make_float4(0,0,0,0); \
                a[2]=make_float4(0,0,0,0); a[3]=make_float4(0,0,0,0); }

__global__ void __launch_bounds__(256) edge_kernel(
    const float* __restrict__ ea, const int* __restrict__ eidx, float* __restrict__ out)
{
    extern __shared__ float sm[];
    float* ssv = sm;                           // 0..16384 (TP phase only)
    unsigned* BBh = (unsigned*)sm;             // post-TP: 0..8704
    unsigned* BBl = (unsigned*)sm + 8704;      // 8704..17408
    unsigned* hAh = (unsigned*)(sm + 17408);   // 1152 (TP phase only)
    unsigned* hAl = (unsigned*)(sm + 18560);   // ..19712
    unsigned* Ah  = (unsigned*)(sm + 19712);   // 32*132
    unsigned* Al  = (unsigned*)(sm + 23936);   // ..28160
    unsigned* Ph  = (unsigned*)(sm + 28160);   // 32*68
    unsigned* Pl  = (unsigned*)(sm + 30336);   // ..32512
    unsigned* Qb  = (unsigned*)(sm + 32512);   // 3 * (2176 h + 2176 l) ..45568
    unsigned* Bsh = (unsigned*)(sm + 45568);   // 128*36 (TP staging)
    unsigned* Bsl = (unsigned*)(sm + 50176);   // ..54784
    float* sea = sm + 54784;                   // 128
    int*   snd = (int*)(sm + 54912);           // 32  -> total 54944 fl
    float* vbuf = sm + 32512;                  // alias Qb (12288 fl needed)

    const float C0n = 0.70710678118654752f;    // sqrt(.5)
    const float C3n = 0.40824829046386302f;    // sqrt(.5)/sqrt(3)

    int t = threadIdx.x, lane = t & 31, w = t >> 5;
    int mtb = (w & 1) * 16, nb = (w >> 1) * 32;
    int gid = lane >> 2, qr = lane & 3;
    int ebase = blockIdx.x * 32;

    if (t < 32) snd[t] = eidx[ebase + t];
    if (t >= 128) sea[t - 128] = ea[ebase * 4 + (t - 128)];
    __syncthreads();
    {   // gather node rows
        int r = t >> 3, q = t & 7;
        const float4* src = (const float4*)g_node + (size_t)snd[r] * 128;
        float4* dst = (float4*)ssv + r * 128;
        #pragma unroll
        for (int j = 0; j < 16; ++j) dst[q + 8 * j] = src[q + 8 * j];
    }
    #pragma unroll
    for (int j = 0; j < 4; ++j) {              // h -> bf16 hi/lo
        int idx = t + 256 * j;
        int e = idx >> 5, k2 = idx & 31;
        float2 hv = *(const float2*)(g_h + (size_t)(ebase + e) * 64 + 2 * k2);
        cvt2(hv.x, hv.y, hAh[e * 36 + k2], hAl[e * 36 + k2]);
    }

    // ---- tpw chunks -> A / P / Q (bf16 A-operands, coefficients folded) ----
    for (int c = 0; c < 4; ++c) {
        __syncthreads();
        #pragma unroll
        for (int j = 0; j < 4; ++j) {          // stage w3 chunk c (stride 36)
            int idx = t + 256 * j;             // < 1024
            int n = idx >> 3, m = idx & 7;
            uint4 a = *(const uint4*)&gw3h[(128 * c + n) * 32 + 4 * m];
            uint4 b = *(const uint4*)&gw3l[(128 * c + n) * 32 + 4 * m];
            *(uint4*)&Bsh[n * 36 + 4 * m] = a;
            *(uint4*)&Bsl[n * 36 + 4 * m] = b;
        }
        __syncthreads();
        float4 cf[4]; Z4(cf);
        gemmK(cf, hAh, hAl, 36, 0, Bsh, Bsl, 36, 0, mtb, nb, lane);
        #pragma unroll
        for (int j = 0; j < 4; ++j) {
            int col = nb + 8 * j + 2 * qr;
            int k2t = col >> 1;
            #pragma unroll
            for (int hh = 0; hh < 2; ++hh) {
                int r = mtb + gid + 8 * hh;
                float cx = hh ? cf[j].z : cf[j].x;
                float cy = hh ? cf[j].w : cf[j].y;
                const float* row = ssv + r * 512;
                float s0 = sea[r * 4];
                unsigned uh, ul;
                if (c == 0) {
                    cvt2(C0n * s0 * cx * row[col], C0n * s0 * cy * row[col + 1], uh, ul);
                    Ah[r * 132 + k2t] = uh; Al[r * 132 + k2t] = ul;
                } else if (c == 1) {
                    cvt2(C0n * cx * row[col], C0n * cy * row[col + 1], uh, ul);
                    Ph[r * 68 + k2t] = uh; Pl[r * 68 + k2t] = ul;
                } else if (c == 2) {
                    float b = C0n * s0;
                    #pragma unroll
                    for (int i = 0; i < 3; ++i) {
                        cvt2(b * cx * row[128 + 128 * i + col],
                             b * cy * row[128 + 128 * i + col + 1], uh, ul);
                        Qb[i * 4352 + r * 68 + k2t] = uh;
                        Qb[i * 4352 + 2176 + r * 68 + k2t] = ul;
                    }
                } else {
                    float s1 = sea[r*4+1], s2 = sea[r*4+2], s3 = sea[r*4+3];
                    float dx = row[128+col]*s1 + row[256+col]*s2 + row[384+col]*s3;
                    float dy = row[129+col]*s1 + row[257+col]*s2 + row[385+col]*s3;
                    cvt2(C3n * cx * dx, C3n * cy * dy, uh, ul);
                    Ah[r * 132 + 64 + k2t] = uh; Al[r * 132 + 64 + k2t] = ul;
                }
            }
        }
    }

    // ---- out_s = A(32x256) @ Wos : two big K=128 stages ----
    {
        float4 cs[4]; Z4(cs);
        for (int s = 0; s < 2; ++s) {
            __syncthreads();                   // prior reads of BB/ssv done
            stageBig(BBh, BBl, gWsh, gWsl, 64 * s, t);
            __syncthreads();
            gemmK(cs, Ah, Al, 132, 64 * s,      BBh, BBl, 68, 0,  mtb, nb, lane);
            gemmK(cs, Ah, Al, 132, 64 * s + 32, BBh, BBl, 68, 32, mtb, nb, lane);
        }
        #pragma unroll
        for (int j = 0; j < 4; ++j) {
            int col = nb + 8 * j + 2 * qr;
            *(float2*)&out[(size_t)(ebase + mtb + gid) * 512 + col] =
                make_float2(cs[j].x, cs[j].y);
            *(float2*)&out[(size_t)(ebase + mtb + gid + 8) * 512 + col] =
                make_float2(cs[j].z, cs[j].w);
        }
    }

    // ---- PV = P @ WvTop : one big K=128 stage ----
    float4 cp[4]; Z4(cp);
    __syncthreads();
    stageBig(BBh, BBl, gWvh, gWvl, 0, t);
    __syncthreads();
    gemmK(cp, Ph, Pl, 68, 0,  BBh, BBl, 68, 0,  mtb, nb, lane);
    gemmK(cp, Ph, Pl, 68, 32, BBh, BBl, 68, 32, mtb, nb, lane);

    // ---- QV_i = (Q*v_i) @ WvBot : one big K=128 stage, 3 gemms ----
    float4 c0[4], c1[4], c2[4]; Z4(c0); Z4(c1); Z4(c2);
    __syncthreads();
    stageBig(BBh, BBl, gWvh, gWvl, 64, t);
    __syncthreads();
    #pragma unroll
    for (int s = 0; s < 2; ++s) {
        gemmK(c0, Qb,        Qb + 2176,  68, 32 * s, BBh, BBl, 68, 32 * s, mtb, nb, lane);
        gemmK(c1, Qb + 4352, Qb + 6528,  68, 32 * s, BBh, BBl, 68, 32 * s, mtb, nb, lane);
        gemmK(c2, Qb + 8704, Qb + 10880, 68, 32 * s, BBh, BBl, 68, 32 * s, mtb, nb, lane);
    }

    // ---- combine into vbuf (aliases Qb) then coalesced store ----
    __syncthreads();                           // all Qb reads complete
    #pragma unroll
    for (int j = 0; j < 4; ++j) {
        int col = nb + 8 * j + 2 * qr;
        #pragma unroll
        for (int hh = 0; hh < 2; ++hh) {
            int r = mtb + gid + 8 * hh;
            float s1 = sea[r*4+1], s2 = sea[r*4+2], s3 = sea[r*4+3];
            float px  = hh ? cp[j].z : cp[j].x,  py  = hh ? cp[j].w : cp[j].y;
            float q0x = hh ? c0[j].z : c0[j].x,  q0y = hh ? c0[j].w : c0[j].y;
            float q1x = hh ? c1[j].z : c1[j].x,  q1y = hh ? c1[j].w : c1[j].y;
            float q2x = hh ? c2[j].z : c2[j].x,  q2y = hh ? c2[j].w : c2[j].y;
            float* o = vbuf + r * 384 + col * 3;
            o[0] = s1 * px + q0x; o[1] = s2 * px + q1x; o[2] = s3 * px + q2x;
            o[3] = s1 * py + q0y; o[4] = s2 * py + q1y; o[5] = s3 * py + q2y;
        }
    }
    __syncthreads();
    float4* vb4 = (float4*)vbuf;
    #pragma unroll
    for (int j = 0; j < 12; ++j) {
        int idx = t + 256 * j;                 // < 3072
        int e = idx / 96, rem = idx % 96;
        ((float4*)out)[(size_t)(ebase + e) * 128 + 32 + rem] = vb4[idx];
    }
}

// ---------------------------------------------------------------------------
extern "C" void kernel_launch(void* const* d_in, const int* in_sizes, int n_in,
                              void* d_out, int out_size) {
    const float* node_feats = (const float*)d_in[0];
    const float* edge_attrs = (const float*)d_in[1];
    const float* edge_feats = (const float*)d_in[2];
    const int*   edge_index = (const int*)d_in[3];
    const float* W_up_s  = (const float*)d_in[4];
    const float* W_up_v  = (const float*)d_in[5];
    const float* mlp_w0  = (const float*)d_in[6];
    const float* mlp_w1  = (const float*)d_in[7];
    const float* mlp_w2  = (const float*)d_in[8];
    const float* mlp_w3  = (const float*)d_in[9];
    const float* W_out_s = (const float*)d_in[10];
    const float* W_out_v = (const float*)d_in[11];
    float* out = (float*)d_out;

    size_t smem1 = (size_t)40960 * 4;   // 160 KB
    size_t smem2 = (size_t)26368 * 4;   // 103 KB
    size_t smem3 = (size_t)54944 * 4;   // 214.6 KB
    cudaFuncSetAttribute(node_kernel, cudaFuncAttributeMaxDynamicSharedMemorySize, (int)smem1);
    cudaFuncSetAttribute(mlp_kernel,  cudaFuncAttributeMaxDynamicSharedMemorySize, (int)smem2);
    cudaFuncSetAttribute(edge_kernel, cudaFuncAttributeMaxDynamicSharedMemorySize, (int)smem3);

    node_kernel<<<148, 256, smem1>>>(node_feats, W_up_s, W_up_v);
    prep_kernel<<<192, 256>>>(mlp_w3, W_out_s, W_out_v);
    mlp_kernel<<<(N_EDGES + 127) / 128, 128, smem2>>>(edge_feats, mlp_w0, mlp_w1, mlp_w2);
    edge_kernel<<<N_EDGES / 32, 256, smem3>>>(edge_attrs, edge_index, out);
}